// round 2
// baseline (speedup 1.0000x reference)
#include <cuda_runtime.h>
#include <cstdint>

// Problem constants: B=32, L=256, C=16, D=128, char vocab = 128.
// out: float32 [2, 32, 128, 256]; out[0]=word conv, out[1]=char feats (transposed).

__device__ float g_Wt_word[3 * 128 * 128];  // [k][din][dout]
__device__ float g_Wt_chr [3 * 128 * 128];  // [k][din][dout]
__device__ float g_P      [128 * 3 * 128];  // [c][k][dout], bias folded into k=1

// ---------------------------------------------------------------------------
// K1: transpose both conv weights [dout][din][k] -> [k][din][dout]
// ---------------------------------------------------------------------------
__global__ void k_transpose(const float* __restrict__ ww, const float* __restrict__ wc) {
    int o = blockIdx.x * 256 + threadIdx.x;
    if (o >= 3 * 128 * 128) return;
    int k = o >> 14;
    int r = o & 16383;
    int din = r >> 7;
    int dout = r & 127;
    int src = dout * 384 + din * 3 + k;
    g_Wt_word[o] = ww[src];
    g_Wt_chr[o]  = wc[src];
}

// ---------------------------------------------------------------------------
// K2: P[c][k][dout] = sum_din chr_table[c,din] * w_chr[dout,din,k]
//     (+ bias folded into the center tap k=1, which every output position has)
// ---------------------------------------------------------------------------
__global__ void k_precomp(const float* __restrict__ chr_table,
                          const float* __restrict__ chr_b) {
    __shared__ float row[128];
    int c = blockIdx.x;
    int d = threadIdx.x;
    row[d] = chr_table[c * 128 + d];
    __syncthreads();
    float a0 = 0.f, a1 = 0.f, a2 = 0.f;
#pragma unroll 8
    for (int i = 0; i < 128; i++) {
        float e = row[i];
        a0 = fmaf(e, g_Wt_chr[          i * 128 + d], a0);
        a1 = fmaf(e, g_Wt_chr[16384 +   i * 128 + d], a1);
        a2 = fmaf(e, g_Wt_chr[32768 +   i * 128 + d], a2);
    }
    g_P[(c * 3 + 0) * 128 + d] = a0;
    g_P[(c * 3 + 1) * 128 + d] = a1 + chr_b[d];
    g_P[(c * 3 + 2) * 128 + d] = a2;
}

// ---------------------------------------------------------------------------
// K3: char path. Block = (batch b, 64-token chunk). P in smem (192 KB).
// Warp handles 8 words; lane owns a dout-quad -> all P reads are
// conflict-free LDS.128. Results staged in smem (pad 65) and written
// coalesced as float4 along the L dimension.
// ---------------------------------------------------------------------------
__global__ void k_char(const int* __restrict__ wic, float* __restrict__ out1) {
    extern __shared__ float sm[];
    float* Ps = sm;              // 49152 floats
    float* Fs = sm + 49152;      // 128 * 65 floats
    int tid = threadIdx.x;       // 256 threads
    int b  = blockIdx.x >> 2;
    int t0 = (blockIdx.x & 3) << 6;

    {   // load P into smem (it lives in L2: 192 KB)
        const float4* src = (const float4*)g_P;
        float4* dst = (float4*)Ps;
#pragma unroll
        for (int i = 0; i < 48; i++) dst[tid + i * 256] = src[tid + i * 256];
    }
    __syncthreads();

    int warp = tid >> 5, lane = tid & 31;
    int d4 = lane << 2;

#define PL(cc, kk) (*(const float4*)&Ps[((cc) * 3 + (kk)) * 128 + d4])

    for (int ii = 0; ii < 8; ii++) {
        int lw = warp * 8 + ii;
        const int4* ip = (const int4*)(wic + (((b << 8) + t0 + lw) << 4));
        int4 q0 = ip[0], q1 = ip[1], q2 = ip[2], q3 = ip[3];
        int c[16] = {q0.x, q0.y, q0.z, q0.w, q1.x, q1.y, q1.z, q1.w,
                     q2.x, q2.y, q2.z, q2.w, q3.x, q3.y, q3.z, q3.w};

        // t = 0: center tap (c0) + right tap (c1); left tap is zero pad
        float4 a = PL(c[0], 1);
        float4 r = PL(c[1], 2);
        float4 m;
        m.x = a.x + r.x; m.y = a.y + r.y; m.z = a.z + r.z; m.w = a.w + r.w;
#pragma unroll
        for (int t = 1; t < 15; t++) {
            float4 ce = PL(c[t], 1);
            float4 le = PL(c[t - 1], 0);
            float4 re = PL(c[t + 1], 2);
            float vx = ce.x + le.x + re.x;
            float vy = ce.y + le.y + re.y;
            float vz = ce.z + le.z + re.z;
            float vw = ce.w + le.w + re.w;
            m.x = fmaxf(m.x, vx); m.y = fmaxf(m.y, vy);
            m.z = fmaxf(m.z, vz); m.w = fmaxf(m.w, vw);
        }
        {   // t = 15: center + left; right tap is zero pad
            float4 ce = PL(c[15], 1);
            float4 le = PL(c[14], 0);
            m.x = fmaxf(m.x, ce.x + le.x); m.y = fmaxf(m.y, ce.y + le.y);
            m.z = fmaxf(m.z, ce.z + le.z); m.w = fmaxf(m.w, ce.w + le.w);
        }
        Fs[(d4 + 0) * 65 + lw] = m.x;
        Fs[(d4 + 1) * 65 + lw] = m.y;
        Fs[(d4 + 2) * 65 + lw] = m.z;
        Fs[(d4 + 3) * 65 + lw] = m.w;
    }
#undef PL
    __syncthreads();

    // Coalesced writeout: out1[b][dout][t0 .. t0+63]
    int dout = tid >> 1;
    int half = tid & 1;
    const float* fsrc = Fs + dout * 65 + (half << 5);
    float* gdst = out1 + (((b << 7) + dout) << 8) + t0 + (half << 5);
#pragma unroll
    for (int i = 0; i < 8; i++) {
        float4 v = make_float4(fsrc[i * 4 + 0], fsrc[i * 4 + 1],
                               fsrc[i * 4 + 2], fsrc[i * 4 + 3]);
        ((float4*)gdst)[i] = v;
    }
}

// ---------------------------------------------------------------------------
// K4: word path GEMM. Block = (b, 64-token tile) x all 128 dout, K=384.
// Emb tile (+halo) in smem; weight taps (64 KB each) double-buffered via
// cp.async. Thread micro-tile 8 tokens x 4 dout -> 32 FFMA per 9 LDS.
// ---------------------------------------------------------------------------
#define CP16(dst_s, src_g) \
    asm volatile("cp.async.cg.shared.global [%0], [%1], 16;\n" :: "r"(dst_s), "l"(src_g))

__global__ void k_word(const int* __restrict__ wv, const float* __restrict__ wtab,
                       const float* __restrict__ wb, float* __restrict__ out0) {
    extern __shared__ float sm[];
    float* Es = sm;            // 66 * 128 floats (token halo)
    float* Ws = sm + 8448;     // 2 * 16384 floats (double-buffered weight tap)
    int tid = threadIdx.x;     // 256 threads
    int b  = blockIdx.x >> 2;
    int t0 = (blockIdx.x & 3) << 6;

    unsigned ws_base = (unsigned)__cvta_generic_to_shared(Ws);
    {   // prefetch tap 0 weights into buffer 0
        const float* g0 = g_Wt_word;
#pragma unroll
        for (int i = 0; i < 16; i++) {
            int o4 = tid + i * 256;
            CP16(ws_base + o4 * 16, g0 + o4 * 4);
        }
        asm volatile("cp.async.commit_group;\n");
    }
    // gather embedding rows for tokens [t0-1, t0+64] (zeros outside the batch row)
    for (int e = tid; e < 66 * 32; e += 256) {
        int s = e >> 5, q = e & 31;
        int t = t0 + s - 1;
        float4 v = make_float4(0.f, 0.f, 0.f, 0.f);
        if ((unsigned)t < 256u) {
            int idx = __ldg(wv + (b << 8) + t);
            v = __ldg((const float4*)wtab + idx * 32 + q);
        }
        ((float4*)Es)[e] = v;
    }
    asm volatile("cp.async.wait_group 0;\n");
    __syncthreads();

    int row = tid >> 5, col = tid & 31;
    int tb = row << 3;
    float acc[8][4];
#pragma unroll
    for (int i = 0; i < 8; i++) {
        acc[i][0] = 0.f; acc[i][1] = 0.f; acc[i][2] = 0.f; acc[i][3] = 0.f;
    }

#pragma unroll
    for (int tap = 0; tap < 3; tap++) {
        if (tap < 2) {  // prefetch next tap into the other buffer
            const float* gn = g_Wt_word + (tap + 1) * 16384;
            unsigned dstb = ws_base + (((tap + 1) & 1) * 16384) * 4;
#pragma unroll
            for (int i = 0; i < 16; i++) {
                int o4 = tid + i * 256;
                CP16(dstb + o4 * 16, gn + o4 * 4);
            }
            asm volatile("cp.async.commit_group;\n");
        }
        const float* W  = Ws + (tap & 1) * 16384;
        const float* Er = Es + (tb + tap) * 128;
#pragma unroll 4
        for (int din = 0; din < 128; din++) {
            float4 w = ((const float4*)(W + din * 128))[col];
#pragma unroll
            for (int i = 0; i < 8; i++) {
                float e = Er[i * 128 + din];
                acc[i][0] = fmaf(e, w.x, acc[i][0]);
                acc[i][1] = fmaf(e, w.y, acc[i][1]);
                acc[i][2] = fmaf(e, w.z, acc[i][2]);
                acc[i][3] = fmaf(e, w.w, acc[i][3]);
            }
        }
        if (tap < 2) {
            asm volatile("cp.async.wait_group 0;\n");
            __syncthreads();
        }
    }

    // epilogue: bias + coalesced float4 stores along L
#pragma unroll
    for (int j = 0; j < 4; j++) {
        int dout = (col << 2) + j;
        float bias = __ldg(wb + dout);
        float* dst = out0 + (((b << 7) + dout) << 8) + t0 + tb;
        float4 lo = make_float4(acc[0][j] + bias, acc[1][j] + bias,
                                acc[2][j] + bias, acc[3][j] + bias);
        float4 hi = make_float4(acc[4][j] + bias, acc[5][j] + bias,
                                acc[6][j] + bias, acc[7][j] + bias);
        ((float4*)dst)[0] = lo;
        ((float4*)dst)[1] = hi;
    }
}

// ---------------------------------------------------------------------------
extern "C" void kernel_launch(void* const* d_in, const int* in_sizes, int n_in,
                              void* d_out, int out_size) {
    const int*   wv   = (const int*)d_in[0];    // word_vector  [32,256]
    const int*   wic  = (const int*)d_in[1];    // words_in_char [32,256,16]
    const float* wtab = (const float*)d_in[2];  // word_table [50000,128]
    const float* ctab = (const float*)d_in[3];  // chr_table [128,128]
    const float* wcw  = (const float*)d_in[4];  // conv_chr_w [128,128,3]
    const float* wcb  = (const float*)d_in[5];  // conv_chr_b [128]
    const float* www  = (const float*)d_in[6];  // conv_word_w [128,128,3]
    const float* wwb  = (const float*)d_in[7];  // conv_word_b [128]
    float* out  = (float*)d_out;
    float* out0 = out;                    // [32,128,256] word conv
    float* out1 = out + 32 * 128 * 256;   // [32,128,256] char feats

    cudaFuncSetAttribute(k_char, cudaFuncAttributeMaxDynamicSharedMemorySize, 229888);
    cudaFuncSetAttribute(k_word, cudaFuncAttributeMaxDynamicSharedMemorySize, 164864);

    k_transpose<<<192, 256>>>(www, wcw);
    k_precomp<<<128, 128>>>(ctab, wcb);
    k_char<<<128, 256, 229888>>>(wic, out1);
    k_word<<<128, 256, 164864>>>(wv, wtab, wwb, out0);
}